// round 12
// baseline (speedup 1.0000x reference)
#include <cuda_runtime.h>

// Problem constants
constexpr int kB = 512;   // batch
constexpr int kL = 128;   // seq len
constexpr int kD = 128;   // model dim
// H = 4 heads of 32

// Scratch (device globals: allocation-free rule)
__device__ float    g_x [kB * kL * kD];               // residual stream, [b][t][d]
__device__ unsigned g_xn[kB * kL * kD];               // LN output, tf32 bit patterns
__device__ float    g_h [kB * kL * kD];               // raw scan output h
__device__ float    g_pre[(size_t)kL * kB * 4 * kD];  // gate preacts, [t][b][g*128+d]
__device__ unsigned g_Wt[2 * 4 * kD * kD];            // W rounded to tf32

typedef unsigned long long ull;

__device__ __forceinline__ float tanh_fast(float x) {
    float y; asm("tanh.approx.f32 %0,%1;" : "=f"(y) : "f"(x)); return y;
}
__device__ __forceinline__ unsigned to_tf32(float f) {
    unsigned u; asm("cvt.rna.tf32.f32 %0, %1;" : "=r"(u) : "f"(f)); return u;
}
__device__ __forceinline__ float tf32f(float f) { return __uint_as_float(to_tf32(f)); }

__device__ __forceinline__ void cp_async16(unsigned smem, const void* gptr) {
    asm volatile("cp.async.cg.shared.global [%0], [%1], 16;" :: "r"(smem), "l"(gptr));
}
__device__ __forceinline__ void cp_commit() {
    asm volatile("cp.async.commit_group;");
}
template<int N>
__device__ __forceinline__ void cp_wait() {
    asm volatile("cp.async.wait_group %0;" :: "n"(N));
}

#define MMA_TF32(C0,C1,C2,C3, A0,A1,A2,A3, B0,B1)                              \
    asm volatile(                                                              \
        "mma.sync.aligned.m16n8k8.row.col.f32.tf32.tf32.f32 "                  \
        "{%0,%1,%2,%3}, {%4,%5,%6,%7}, {%8,%9}, {%0,%1,%2,%3};"                \
        : "+f"(C0), "+f"(C1), "+f"(C2), "+f"(C3)                               \
        : "r"(A0), "r"(A1), "r"(A2), "r"(A3), "r"(B0), "r"(B1))

// ---------------------------------------------------------------------------
// W -> tf32 pre-round (both layers, once per launch)
// ---------------------------------------------------------------------------
__global__ void k_wcvt(const float* __restrict__ Wg) {
    int i = blockIdx.x * 256 + threadIdx.x;
    #pragma unroll
    for (int j = 0; j < 4; j++) {
        int e = i * 4 + j;
        g_Wt[e] = to_tf32(__ldg(&Wg[e]));
    }
}

// ---------------------------------------------------------------------------
// Fused embedding gather + LayerNorm(layer0). One warp per row of 128.
// ---------------------------------------------------------------------------
__global__ void k_embed_ln(const int* __restrict__ ids, const float4* __restrict__ emb,
                           const float* __restrict__ w, const float* __restrict__ bb) {
    int t    = blockIdx.x * 256 + threadIdx.x;
    int row  = t >> 5;
    int lane = t & 31;
    int id   = __ldg(&ids[row]);
    float4 v = emb[(size_t)id * 32 + lane];
    ((float4*)g_x)[(size_t)row * 32 + lane] = v;
    float s = v.x + v.y + v.z + v.w;
    float q = v.x*v.x + v.y*v.y + v.z*v.z + v.w*v.w;
    #pragma unroll
    for (int o = 16; o; o >>= 1) {
        s += __shfl_xor_sync(0xffffffffu, s, o);
        q += __shfl_xor_sync(0xffffffffu, q, o);
    }
    float mu  = s * (1.f / 128.f);
    float var = fmaxf(q * (1.f / 128.f) - mu * mu, 0.f);
    float rs  = rsqrtf(var + 1e-5f);
    float4 wv = ((const float4*)w)[lane];
    float4 bv = ((const float4*)bb)[lane];
    uint4 o4;
    o4.x = to_tf32((v.x - mu) * rs * wv.x + bv.x);
    o4.y = to_tf32((v.y - mu) * rs * wv.y + bv.y);
    o4.z = to_tf32((v.z - mu) * rs * wv.z + bv.z);
    o4.w = to_tf32((v.w - mu) * rs * wv.w + bv.w);
    ((uint4*)g_xn)[(size_t)row * 32 + lane] = o4;
}

// ---------------------------------------------------------------------------
// Fused GroupNorm + residual (+ optional LayerNorm->tf32 for next layer).
// ---------------------------------------------------------------------------
template<bool DO_LN>
__global__ void k_gn(const float* __restrict__ gnw,
                     const float* __restrict__ lnw, const float* __restrict__ lnb) {
    const unsigned FULL = 0xffffffffu;
    int t    = blockIdx.x * 256 + threadIdx.x;
    int row  = t >> 5;
    int lane = t & 31;
    float4 hv = ((const float4*)g_h)[(size_t)row * 32 + lane];
    float4 xv = ((const float4*)g_x)[(size_t)row * 32 + lane];
    float s = hv.x + hv.y + hv.z + hv.w;
    float q = hv.x*hv.x + hv.y*hv.y + hv.z*hv.z + hv.w*hv.w;
    #pragma unroll
    for (int o = 1; o < 8; o <<= 1) {
        s += __shfl_xor_sync(FULL, s, o);
        q += __shfl_xor_sync(FULL, q, o);
    }
    float mu  = s * (1.f / 32.f);
    float var = fmaxf(q * (1.f / 32.f) - mu * mu, 0.f);
    float rs  = rsqrtf(var + 1e-5f);
    float4 gw = ((const float4*)gnw)[lane];
    float4 xp;
    xp.x = xv.x + (hv.x - mu) * rs * gw.x;
    xp.y = xv.y + (hv.y - mu) * rs * gw.y;
    xp.z = xv.z + (hv.z - mu) * rs * gw.z;
    xp.w = xv.w + (hv.w - mu) * rs * gw.w;
    ((float4*)g_x)[(size_t)row * 32 + lane] = xp;

    if (DO_LN) {
        float s2 = xp.x + xp.y + xp.z + xp.w;
        float q2 = xp.x*xp.x + xp.y*xp.y + xp.z*xp.z + xp.w*xp.w;
        #pragma unroll
        for (int o = 16; o; o >>= 1) {
            s2 += __shfl_xor_sync(FULL, s2, o);
            q2 += __shfl_xor_sync(FULL, q2, o);
        }
        float mu2  = s2 * (1.f / 128.f);
        float var2 = fmaxf(q2 * (1.f / 128.f) - mu2 * mu2, 0.f);
        float rs2  = rsqrtf(var2 + 1e-5f);
        float4 wv = ((const float4*)lnw)[lane];
        float4 bv = ((const float4*)lnb)[lane];
        uint4 o4;
        o4.x = to_tf32((xp.x - mu2) * rs2 * wv.x + bv.x);
        o4.y = to_tf32((xp.y - mu2) * rs2 * wv.y + bv.y);
        o4.z = to_tf32((xp.z - mu2) * rs2 * wv.z + bv.z);
        o4.w = to_tf32((xp.w - mu2) * rs2 * wv.w + bv.w);
        ((uint4*)g_xn)[(size_t)row * 32 + lane] = o4;
    }
}

// ---------------------------------------------------------------------------
// tf32 input GEMM (round-11): K tiled into 4 chunks of 32, double-buffered,
// __launch_bounds__(256,2) -> 2 CTAs/SM. grid (4, 512): bn = gate, bm = batch.
// ---------------------------------------------------------------------------
constexpr int GSTR = 36;
constexpr int GEMM_SMEM = 4 * 128 * GSTR * 4;

__global__ void __launch_bounds__(256, 2) k_gemm(int layer,
                                                 const float* __restrict__ bias) {
    extern __shared__ unsigned sh[];
    unsigned* As0 = sh;
    unsigned* As1 = sh + 128 * GSTR;
    unsigned* Bs0 = sh + 2 * 128 * GSTR;
    unsigned* Bs1 = sh + 3 * 128 * GSTR;

    int tid = threadIdx.x;
    int bn  = blockIdx.x;
    int bm  = blockIdx.y;

    const unsigned* Ag = g_xn + (size_t)bm * 128 * 128;
    const unsigned* Wg = g_Wt + (size_t)(layer * 4 + bn) * 128 * 128;
    unsigned As_u[2] = { (unsigned)__cvta_generic_to_shared(As0),
                         (unsigned)__cvta_generic_to_shared(As1) };
    unsigned Bs_u[2] = { (unsigned)__cvta_generic_to_shared(Bs0),
                         (unsigned)__cvta_generic_to_shared(Bs1) };

    auto issue = [&](int buf, int kc) {
        #pragma unroll
        for (int i = 0; i < 4; i++) {
            int e = i * 256 + tid, rr = e >> 3, cc = e & 7;
            cp_async16(As_u[buf] + (rr * GSTR + cc * 4) * 4,
                       Ag + rr * 128 + kc * 32 + cc * 4);
            cp_async16(Bs_u[buf] + (rr * GSTR + cc * 4) * 4,
                       Wg + rr * 128 + kc * 32 + cc * 4);
        }
        cp_commit();
    };
    issue(0, 0);
    issue(1, 1);

    int warp = tid >> 5, lane = tid & 31;
    int wm = warp >> 2, wn = warp & 3;
    int gid = lane >> 2, tg = lane & 3;

    float bz[4][2];
    #pragma unroll
    for (int j = 0; j < 4; j++) {
        int col = bn * 128 + wn * 32 + j * 8 + tg * 2;
        bz[j][0] = __ldg(&bias[col]);
        bz[j][1] = __ldg(&bias[col + 1]);
    }

    float acc[4][4][4];
    #pragma unroll
    for (int i = 0; i < 4; i++)
        #pragma unroll
        for (int j = 0; j < 4; j++)
            #pragma unroll
            for (int c = 0; c < 4; c++) acc[i][j][c] = 0.f;

    #pragma unroll
    for (int kc = 0; kc < 4; kc++) {
        unsigned* As = (kc & 1) ? As1 : As0;
        unsigned* Bs = (kc & 1) ? Bs1 : Bs0;
        if (kc < 3) cp_wait<1>(); else cp_wait<0>();
        __syncthreads();

        #pragma unroll
        for (int ks = 0; ks < 4; ks++) {
            int k0 = ks * 8 + tg;
            unsigned a[4][4], bf[4][2];
            #pragma unroll
            for (int i = 0; i < 4; i++) {
                int r0 = wm * 64 + i * 16 + gid;
                a[i][0] = As[r0 * GSTR + k0];
                a[i][1] = As[(r0 + 8) * GSTR + k0];
                a[i][2] = As[r0 * GSTR + k0 + 4];
                a[i][3] = As[(r0 + 8) * GSTR + k0 + 4];
            }
            #pragma unroll
            for (int j = 0; j < 4; j++) {
                int n0 = wn * 32 + j * 8 + gid;
                bf[j][0] = Bs[n0 * GSTR + k0];
                bf[j][1] = Bs[n0 * GSTR + k0 + 4];
            }
            #pragma unroll
            for (int i = 0; i < 4; i++)
                #pragma unroll
                for (int j = 0; j < 4; j++)
                    MMA_TF32(acc[i][j][0], acc[i][j][1], acc[i][j][2], acc[i][j][3],
                             a[i][0], a[i][1], a[i][2], a[i][3],
                             bf[j][0], bf[j][1]);
        }
        __syncthreads();

        if (kc + 2 < 4) issue(kc & 1, kc + 2);
    }

    #pragma unroll
    for (int i = 0; i < 4; i++) {
        int la = wm * 64 + i * 16 + gid;
        int lb = la + 8;
        float* outa = g_pre + ((size_t)la * 512 + bm) * 512;
        float* outb = g_pre + ((size_t)lb * 512 + bm) * 512;
        #pragma unroll
        for (int j = 0; j < 4; j++) {
            int col = bn * 128 + wn * 32 + j * 8 + tg * 2;
            *(float2*)&outa[col] = make_float2(acc[i][j][0] + bz[j][0], acc[i][j][1] + bz[j][1]);
            *(float2*)&outb[col] = make_float2(acc[i][j][2] + bz[j][0], acc[i][j][3] + bz[j][1]);
        }
    }
}

// ---------------------------------------------------------------------------
// sLSTM gate math: 5 MUFU (3 ex2 + tanh + rcp)
// ---------------------------------------------------------------------------
__device__ __forceinline__ void gate_step(float ai, float af, float az, float ao,
                                          float& h, float& c, float& n, float& m) {
    float fm = af + m;
    float mn = fmaxf(fm, ai);
    float iv = __expf(ai - mn);
    float fv = __expf(fm - mn);
    float th = tanh_fast(az);
    c = fmaf(fv, c, iv * th);
    n = fmaf(fv, n, iv);
    float eo = __expf(-ao);                   // h = sigmoid(ao) * c / n
    float denom = fmaf(n, eo, n);             //   = c / (n * (1 + e^-ao))
    h = __fdividef(c, denom);
    m = mn;
}

// ---------------------------------------------------------------------------
// Tensor-core recurrent scan. Grid 128 x 256 (8 warps), 4 batches/CTA.
// warp = (head hh, dim-half mhalf). M-tile mt = gate g; rows of tile = dims
// mhalf*16 + gid (+8). N: batch b sits at column 2b (odd cols zero) so the
// C fragment gives each thread all 4 gates of (d, b=tg) in c[mt][0] and of
// (d+8, b=tg) in c[mt][2] -> gate math directly on fragments.
// A = rna-tf32(R^T), stationary in registers. B = h, hi/lo tf32 split via
// double-buffered smem (products exact in fp32 -> recurrence error ~6e-5).
// One 64-thread named barrier per step (pairs decoupled).
// ---------------------------------------------------------------------------
__global__ void __launch_bounds__(256, 1) k_scan(const float* __restrict__ R) {
    __shared__ float sh_hi[2][4][32][8];      // [slot][head][k(dim)][ncol]
    __shared__ float sh_lo[2][4][32][8];

    int tid   = threadIdx.x;
    int warp  = tid >> 5, lane = tid & 31;
    int hh    = warp >> 1;                    // head
    int mhalf = warp & 1;                     // dim half
    int gid   = lane >> 2, tg = lane & 3;

    int bglob = blockIdx.x * 4 + tg;          // this thread's batch
    int dA    = mhalf * 16 + gid;             // dims this thread owns
    int dB    = dA + 8;
    int oA    = hh * 32 + dA;
    int oB    = hh * 32 + dB;

    // zero smem (covers odd columns + initial h = 0)
    #pragma unroll
    for (int i = 0; i < 8; i++) {
        ((float*)sh_hi)[i * 256 + tid] = 0.f;
        ((float*)sh_lo)[i * 256 + tid] = 0.f;
    }

    // Stationary A fragments: A[r][k] = R[g][hh][k][d], r=(g,d), rna tf32.
    // Afrag[mt=g][kt][0..3]
    unsigned Af[4][4][4];
    #pragma unroll
    for (int g = 0; g < 4; g++)
        #pragma unroll
        for (int kt = 0; kt < 4; kt++) {
            int k0 = kt * 8 + tg;
            const float* Rb = R + ((size_t)(g * 4 + hh) * 32) * 32;
            Af[g][kt][0] = to_tf32(__ldg(&Rb[(k0)     * 32 + dA]));
            Af[g][kt][1] = to_tf32(__ldg(&Rb[(k0)     * 32 + dB]));
            Af[g][kt][2] = to_tf32(__ldg(&Rb[(k0 + 4) * 32 + dA]));
            Af[g][kt][3] = to_tf32(__ldg(&Rb[(k0 + 4) * 32 + dB]));
        }

    float cA = 0.f, nA = 0.f, mA = 0.f;
    float cB = 0.f, nB = 0.f, mB = 0.f;

    // pre pointers: pre[(t*512 + b)*512 + g*128 + o]
    const float* pbase = g_pre + (size_t)bglob * 512;
    float preA[4], preB[4];
    #pragma unroll
    for (int g = 0; g < 4; g++) {
        preA[g] = pbase[g * 128 + oA];
        preB[g] = pbase[g * 128 + oB];
    }
    float* hoA = g_h + (size_t)bglob * kL * kD + oA;
    float* hoB = g_h + (size_t)bglob * kL * kD + oB;

    __syncthreads();                          // smem zeroing visible

    for (int t = 0; t < kL; t++) {
        int s = t & 1;

        // B fragments from smem (hi + lo)
        unsigned bhi[4][2], blo[4][2];
        #pragma unroll
        for (int kt = 0; kt < 4; kt++) {
            int k0 = kt * 8 + tg;
            bhi[kt][0] = __float_as_uint(sh_hi[s][hh][k0][gid]);
            bhi[kt][1] = __float_as_uint(sh_hi[s][hh][k0 + 4][gid]);
            blo[kt][0] = __float_as_uint(sh_lo[s][hh][k0][gid]);
            blo[kt][1] = __float_as_uint(sh_lo[s][hh][k0 + 4][gid]);
        }

        // C seeded with the preactivations
        float C[4][4];
        #pragma unroll
        for (int g = 0; g < 4; g++) {
            C[g][0] = preA[g]; C[g][1] = 0.f;
            C[g][2] = preB[g]; C[g][3] = 0.f;
        }

        // prefetch next step's pre
        if (t + 1 < kL) {
            const float* pn = pbase + (size_t)(t + 1) * (kB * 512);
            #pragma unroll
            for (int g = 0; g < 4; g++) {
                preA[g] = pn[g * 128 + oA];
                preB[g] = pn[g * 128 + oB];
            }
        }

        // rec = R^T h : 32 mma (hi then lo)
        #pragma unroll
        for (int kt = 0; kt < 4; kt++)
            #pragma unroll
            for (int g = 0; g < 4; g++)
                MMA_TF32(C[g][0], C[g][1], C[g][2], C[g][3],
                         Af[g][kt][0], Af[g][kt][1], Af[g][kt][2], Af[g][kt][3],
                         bhi[kt][0], bhi[kt][1]);
        #pragma unroll
        for (int kt = 0; kt < 4; kt++)
            #pragma unroll
            for (int g = 0; g < 4; g++)
                MMA_TF32(C[g][0], C[g][1], C[g][2], C[g][3],
                         Af[g][kt][0], Af[g][kt][1], Af[g][kt][2], Af[g][kt][3],
                         blo[kt][0], blo[kt][1]);

        // gate math directly on fragments
        float hA, hB;
        gate_step(C[0][0], C[1][0], C[2][0], C[3][0], hA, cA, nA, mA);
        gate_step(C[0][2], C[1][2], C[2][2], C[3][2], hB, cB, nB, mB);

        hoA[(size_t)t * kD] = hA;
        hoB[(size_t)t * kD] = hB;

        // hi/lo split into the other slot (batch b -> column 2b)
        int s2 = s ^ 1;
        float hAhi = tf32f(hA), hBhi = tf32f(hB);
        sh_hi[s2][hh][dA][2 * tg] = hAhi;
        sh_lo[s2][hh][dA][2 * tg] = tf32f(hA - hAhi);
        sh_hi[s2][hh][dB][2 * tg] = hBhi;
        sh_lo[s2][hh][dB][2 * tg] = tf32f(hB - hBhi);

        // pair barrier: warps (hh,0) and (hh,1) = 64 contiguous threads
        asm volatile("bar.sync %0, 64;" :: "r"(1 + hh) : "memory");
    }
}

// ---------------------------------------------------------------------------
// Head: mean over time, then 128->64 ReLU MLP, then 64->2
// ---------------------------------------------------------------------------
__global__ void k_head(const float* __restrict__ w1, const float* __restrict__ b1,
                       const float* __restrict__ w2, const float* __restrict__ b2,
                       float* __restrict__ out) {
    __shared__ float pooled[128];
    __shared__ float hid[64];
    int b = blockIdx.x, o = threadIdx.x;
    const float* xb = g_x + (size_t)b * kL * kD + o;
    float s = 0.f;
    #pragma unroll 8
    for (int t = 0; t < kL; t++) s += xb[(size_t)t * kD];
    pooled[o] = s * (1.f / 128.f);
    __syncthreads();
    if (o < 64) {
        float a = __ldg(&b1[o]);
        const float* wr = w1 + o * 128;
        #pragma unroll
        for (int d = 0; d < 128; d++) a = fmaf(pooled[d], __ldg(&wr[d]), a);
        hid[o] = fmaxf(a, 0.f);
    }
    __syncthreads();
    if (o < 2) {
        float a = __ldg(&b2[o]);
        const float* wr = w2 + o * 64;
        #pragma unroll
        for (int j = 0; j < 64; j++) a = fmaf(hid[j], __ldg(&wr[j]), a);
        out[b * 2 + o] = a;
    }
}

// ---------------------------------------------------------------------------
extern "C" void kernel_launch(void* const* d_in, const int* in_sizes, int n_in,
                              void* d_out, int out_size) {
    const int*   ids  = (const int*)  d_in[0];
    const float* emb  = (const float*)d_in[1];
    const float* ln_w = (const float*)d_in[2];
    const float* ln_b = (const float*)d_in[3];
    const float* Wg   = (const float*)d_in[4];
    const float* Rg   = (const float*)d_in[5];
    const float* bg   = (const float*)d_in[6];
    const float* gn_w = (const float*)d_in[7];
    const float* w1   = (const float*)d_in[8];
    const float* b1   = (const float*)d_in[9];
    const float* w2   = (const float*)d_in[10];
    const float* b2   = (const float*)d_in[11];
    float* out = (float*)d_out;

    cudaFuncSetAttribute(k_gemm, cudaFuncAttributeMaxDynamicSharedMemorySize, GEMM_SMEM);

    const int ROWS = kB * kL;                      // 65536 rows of 128

    k_wcvt<<<128, 256>>>(Wg);                      // both layers' W -> tf32
    k_embed_ln<<<ROWS / 8, 256>>>(ids, (const float4*)emb, ln_w, ln_b);

    // layer 0
    k_gemm<<<dim3(4, 512), 256, GEMM_SMEM>>>(0, bg);
    k_scan<<<128, 256>>>(Rg);
    k_gn<true><<<ROWS / 8, 256>>>(gn_w, ln_w + 128, ln_b + 128);

    // layer 1
    k_gemm<<<dim3(4, 512), 256, GEMM_SMEM>>>(1, bg + 512);
    k_scan<<<128, 256>>>(Rg + (size_t)4 * 4 * 32 * 32);
    k_gn<false><<<ROWS / 8, 256>>>(gn_w + 128, nullptr, nullptr);

    k_head<<<512, 128>>>(w1, b1, w2, b2, out);
}